// round 7
// baseline (speedup 1.0000x reference)
#include <cuda_runtime.h>
#include <cuda_fp16.h>
#include <math.h>

constexpr int  B_ = 256, T_ = 512, I_ = 128, H_ = 256, L_ = 64, P_ = 50;
constexpr long BT = (long)B_ * T_;

constexpr long XHAT_OFF = 0;
constexpr long PMU_OFF  = BT * I_;
constexpr long PLV_OFF  = PMU_OFF + BT * L_;
constexpr long QMU_OFF  = PLV_OFF + BT * L_;
constexpr long QLV_OFF  = QMU_OFF + BT * L_;

// device-global scratch (static; no allocation APIs)
__device__ float g_H[BT * H_];
__device__ float g_Z[BT * L_];
__device__ float g_preQM[BT * P_];
__device__ float g_preQL[BT * P_];
__device__ float g_preH[BT * P_];

// ======================= Phase A: x pre-projections =======================
constexpr int ROWS_A = 64;
constexpr int XS = 132;
constexpr size_t SMEM_PRE = (size_t)(3 * P_ * XS + ROWS_A * XS + 3 * 64) * sizeof(float);

__global__ __launch_bounds__(256, 1) void k_pre(
    const float* __restrict__ x,
    const float* __restrict__ Wqm1, const float* __restrict__ bqm1,
    const float* __restrict__ Wql1, const float* __restrict__ bql1,
    const float* __restrict__ Wh1,  const float* __restrict__ bh1)
{
    extern __shared__ float sm[];
    float* sw = sm;                   // [3][50][132]
    float* sx = sw + 3 * P_ * XS;     // [64][132]
    float* sb = sx + ROWS_A * XS;     // [3][64]
    const int tid = threadIdx.x;
    const long bt0 = (long)blockIdx.x * ROWS_A;

    for (int idx = tid; idx < P_ * I_; idx += 256) {
        int j = idx >> 7, i = idx & 127;
        sw[(0 * P_ + j) * XS + i] = Wqm1[j * 384 + i];
        sw[(1 * P_ + j) * XS + i] = Wql1[j * 384 + i];
        sw[(2 * P_ + j) * XS + i] = Wh1 [j * 448 + i];
    }
    for (int idx = tid; idx < ROWS_A * I_; idx += 256) {
        int r = idx >> 7, i = idx & 127;
        sx[r * XS + i] = x[bt0 * I_ + idx];
    }
    if (tid < P_) { sb[tid] = bqm1[tid]; sb[64 + tid] = bql1[tid]; sb[128 + tid] = bh1[tid]; }
    __syncthreads();

    for (int task = tid; task < ROWS_A * 150; task += 256) {
        int r = task / 150; int mj = task - r * 150; int m = mj / P_; int j = mj - m * P_;
        const float4* w4 = reinterpret_cast<const float4*>(sw + (m * P_ + j) * XS);
        const float4* x4 = reinterpret_cast<const float4*>(sx + r * XS);
        float acc = sb[m * 64 + j];
        #pragma unroll 8
        for (int k = 0; k < I_ / 4; k++) {
            float4 wv = w4[k], xv = x4[k];
            acc += wv.x * xv.x + wv.y * xv.y + wv.z * xv.z + wv.w * xv.w;
        }
        float* dst = (m == 0) ? g_preQM : (m == 1) ? g_preQL : g_preH;
        dst[(bt0 + r) * P_ + j] = acc;
    }
}

// ======================= Phase B: sequential recurrence =======================
constexpr int WS = 260;  // 65x16B rows -> conflict-free LDS.128
constexpr int O_W1  = 0;                    // 3*50*260
constexpr int O_W2  = O_W1 + 3 * P_ * WS;   // 2*64*50
constexpr int O_B2  = O_W2 + 2 * L_ * P_;   // 128
constexpr int O_BH2 = O_B2 + 128;           // 256
constexpr int O_H   = O_BH2 + 256;          // 2*2*260
constexpr int O_AMU = O_H + 2 * 2 * WS;
constexpr int O_ALV = O_AMU + 104;
constexpr int O_VH  = O_ALV + 104;
constexpr int O_AH  = O_VH + 104;
constexpr int O_QMU = O_AH + 104;
constexpr int O_ELV = O_QMU + 128;
constexpr int O_Z   = O_ELV + 128;
constexpr int O_ENDF = O_Z + 128;
constexpr size_t SEQ_HALF_OFF = (size_t)O_ENDF * sizeof(float);
constexpr size_t SMEM_SEQ = SEQ_HALF_OFF + (size_t)(L_ * P_ + P_ * H_) * sizeof(__half);

__global__ __launch_bounds__(256, 1) void k_seq(
    const float* __restrict__ hidden, const float* __restrict__ noise,
    const float* __restrict__ Wqm1, const float* __restrict__ Wqm2, const float* __restrict__ bqm2,
    const float* __restrict__ Wql1, const float* __restrict__ Wql2, const float* __restrict__ bql2,
    const float* __restrict__ Wh1,  const float* __restrict__ Wh2,  const float* __restrict__ bh2,
    float* __restrict__ out)
{
    extern __shared__ float sm[];
    float* sW1  = sm + O_W1;  float* sW2  = sm + O_W2;
    float* sb2  = sm + O_B2;  float* sbh2 = sm + O_BH2;
    float* sH   = sm + O_H;
    float* sAMU = sm + O_AMU; float* sALV = sm + O_ALV;
    float* sVH  = sm + O_VH;  float* sAH  = sm + O_AH;
    float* sQMU = sm + O_QMU; float* sELV = sm + O_ELV; float* sZ = sm + O_Z;
    __half* sWzt = reinterpret_cast<__half*>(reinterpret_cast<char*>(sm) + SEQ_HALF_OFF); // [n][j]
    __half* sWh2 = sWzt + L_ * P_;  // [j][k] transposed

    const int tid = threadIdx.x;
    const int r0 = blockIdx.x * 2;

    for (int idx = tid; idx < P_ * H_; idx += 256) {
        int j = idx >> 8, k = idx & 255;
        sW1[(0 * P_ + j) * WS + k] = Wqm1[j * 384 + 128 + k];
        sW1[(1 * P_ + j) * WS + k] = Wql1[j * 384 + 128 + k];
        sW1[(2 * P_ + j) * WS + k] = Wh1 [j * 448 + 128 + k];
        sWh2[j * H_ + k] = __float2half(Wh2[k * P_ + j]);
    }
    for (int idx = tid; idx < L_ * P_; idx += 256) {
        int n = idx / P_, j = idx - n * P_;
        sW2[idx]           = Wqm2[idx];
        sW2[L_ * P_ + idx] = Wql2[idx];
        sWzt[n * P_ + j]   = __float2half(Wh1[j * 448 + 384 + n]);
    }
    if (tid < L_) { sb2[tid] = bqm2[tid]; sb2[64 + tid] = bql2[tid]; }
    if (tid < H_) sbh2[tid] = bh2[tid];
    for (int idx = tid; idx < 2 * H_; idx += 256) {
        int r = idx >> 8, k = idx & 255;
        sH[r * WS + k] = hidden[(r0 + r) * H_ + k];
    }
    __syncthreads();

    int cb = 0;
    for (int t = 0; t < T_; t++) {
        const long bt0 = (long)r0 * T_ + t;
        const long bt1 = bt0 + T_;

        float eps = 0.f;
        if (tid < 128) {
            int r = tid >> 6, n = tid & 63;
            eps = noise[(r ? bt1 : bt0) * L_ + n];
        }

        // stage 1: three 256->50 projections vs h
        for (int task = tid; task < 300; task += 256) {
            int m = task / 100; int rj = task - m * 100; int r = rj / P_; int j = rj - r * P_;
            const long bt = r ? bt1 : bt0;
            const float* preArr = (m == 0) ? g_preQM : (m == 1) ? g_preQL : g_preH;
            float pre = preArr[bt * P_ + j];
            const float4* w4 = reinterpret_cast<const float4*>(sW1 + (m * P_ + j) * WS);
            const float4* h4 = reinterpret_cast<const float4*>(sH + (cb * 2 + r) * WS);
            float acc = 0.f;
            #pragma unroll 8
            for (int k = 0; k < H_ / 4; k++) {
                float4 wv = w4[k], hv = h4[k];
                acc += wv.x * hv.x + wv.y * hv.y + wv.z * hv.z + wv.w * hv.w;
            }
            float u = pre + acc;
            if (m == 0)      sAMU[r * 52 + j] = fmaxf(u, 0.f);
            else if (m == 1) sALV[r * 52 + j] = fmaxf(u, 0.f);
            else             sVH [r * 52 + j] = u;   // relu after z-part added
        }
        __syncthreads();

        // stage 2: q_mu / q_lv (50 -> 64)
        {
            int branch = tid >> 7; int r = (tid >> 6) & 1; int n = tid & 63;
            const float* w = sW2 + (branch * L_ + n) * P_;
            const float* a = (branch == 0 ? sAMU : sALV) + r * 52;
            float acc = sb2[branch * 64 + n];
            #pragma unroll
            for (int j = 0; j < P_; j++) acc += w[j] * a[j];
            const long bt = r ? bt1 : bt0;
            if (branch == 0) { out[QMU_OFF + bt * L_ + n] = acc; sQMU[r * 64 + n] = acc; }
            else             { out[QLV_OFF + bt * L_ + n] = acc; sELV[r * 64 + n] = __expf(0.5f * acc); }
        }
        __syncthreads();

        // stage 2b: z; store pre-update h to history
        if (tid < 128) {
            int r = tid >> 6, n = tid & 63;
            const long bt = r ? bt1 : bt0;
            float z = sQMU[r * 64 + n] + sELV[r * 64 + n] * eps;
            sZ[r * 64 + n] = z;
            g_Z[bt * L_ + n] = z;
        }
        for (int q = tid; q < 2 * H_; q += 256) {
            int r = q >> 8, k = q & 255;
            g_H[(r ? bt1 : bt0) * H_ + k] = sH[(cb * 2 + r) * WS + k];
        }
        __syncthreads();

        // stage 3: add z-part, relu
        if (tid < 100) {
            int r = tid / P_, j = tid - r * P_;
            float v = sVH[r * 52 + j];
            const float* zr = sZ + r * 64;
            #pragma unroll
            for (int n = 0; n < L_; n++) v += __half2float(sWzt[n * P_ + j]) * zr[n];
            sAH[r * 52 + j] = fmaxf(v, 0.f);
        }
        __syncthreads();

        // stage 4: h_next = Wh2 @ a + bh2
        {
            int r = tid >> 7; int kp = tid & 127;
            const __half2* w2 = reinterpret_cast<const __half2*>(sWh2) + kp;
            const float* a = sAH + r * 52;
            float accx = sbh2[2 * kp], accy = sbh2[2 * kp + 1];
            #pragma unroll
            for (int j = 0; j < P_; j++) {
                float2 wf = __half22float2(w2[j * 128]);
                float aj = a[j];
                accx += wf.x * aj; accy += wf.y * aj;
            }
            int nb = cb ^ 1;
            sH[(nb * 2 + r) * WS + 2 * kp]     = accx;
            sH[(nb * 2 + r) * WS + 2 * kp + 1] = accy;
        }
        __syncthreads();
        cb ^= 1;
    }
}

// ======================= Phase C1: p-branch MLPs =======================
constexpr int ROWS_P = 32;
constexpr int PO_W1 = 0;
constexpr int PO_W2 = PO_W1 + 2 * P_ * WS;
constexpr int PO_B1 = PO_W2 + 2 * L_ * P_;
constexpr int PO_B2 = PO_B1 + 128;
constexpr int PO_H  = PO_B2 + 128;
constexpr int PO_A  = PO_H + ROWS_P * WS;
constexpr size_t SMEM_P = (size_t)(PO_A + 2 * ROWS_P * 52) * sizeof(float);

__global__ __launch_bounds__(256, 1) void k_pbranch(
    const float* __restrict__ Wpm1, const float* __restrict__ bpm1,
    const float* __restrict__ Wpm2, const float* __restrict__ bpm2,
    const float* __restrict__ Wpl1, const float* __restrict__ bpl1,
    const float* __restrict__ Wpl2, const float* __restrict__ bpl2,
    float* __restrict__ out)
{
    extern __shared__ float sm[];
    float* sW1 = sm + PO_W1; float* sW2 = sm + PO_W2;
    float* sb1 = sm + PO_B1; float* sb2 = sm + PO_B2;
    float* sh  = sm + PO_H;  float* sa  = sm + PO_A;
    const int tid = threadIdx.x;
    const long bt0 = (long)blockIdx.x * ROWS_P;

    for (int idx = tid; idx < P_ * H_; idx += 256) {
        int j = idx >> 8, k = idx & 255;
        sW1[(0 * P_ + j) * WS + k] = Wpm1[idx];
        sW1[(1 * P_ + j) * WS + k] = Wpl1[idx];
    }
    for (int idx = tid; idx < L_ * P_; idx += 256) {
        sW2[idx]           = Wpm2[idx];
        sW2[L_ * P_ + idx] = Wpl2[idx];
    }
    if (tid < P_) { sb1[tid] = bpm1[tid]; sb1[64 + tid] = bpl1[tid]; }
    if (tid < L_) { sb2[tid] = bpm2[tid]; sb2[64 + tid] = bpl2[tid]; }
    for (int idx = tid; idx < ROWS_P * H_; idx += 256) {
        int r = idx >> 8, k = idx & 255;
        sh[r * WS + k] = g_H[bt0 * H_ + idx];
    }
    __syncthreads();

    for (int task = tid; task < 2 * ROWS_P * P_; task += 256) {
        int m = task / (ROWS_P * P_); int rj = task - m * ROWS_P * P_;
        int r = rj / P_; int j = rj - r * P_;
        const float4* w4 = reinterpret_cast<const float4*>(sW1 + (m * P_ + j) * WS);
        const float4* h4 = reinterpret_cast<const float4*>(sh + r * WS);
        float acc = sb1[m * 64 + j];
        #pragma unroll 8
        for (int k = 0; k < H_ / 4; k++) {
            float4 wv = w4[k], hv = h4[k];
            acc += wv.x * hv.x + wv.y * hv.y + wv.z * hv.z + wv.w * hv.w;
        }
        sa[(m * ROWS_P + r) * 52 + j] = fmaxf(acc, 0.f);
    }
    __syncthreads();

    for (int task = tid; task < 2 * ROWS_P * L_; task += 256) {
        int m = task / (ROWS_P * L_); int rn = task - m * ROWS_P * L_;
        int r = rn >> 6; int n = rn & 63;
        const float* w = sW2 + (m * L_ + n) * P_;
        const float* a = sa + (m * ROWS_P + r) * 52;
        float acc = sb2[m * 64 + n];
        #pragma unroll
        for (int j = 0; j < P_; j++) acc += w[j] * a[j];
        long off = (m == 0) ? PMU_OFF : PLV_OFF;
        out[off + (bt0 + r) * L_ + n] = acc;
    }
}

// ======================= Phase C2: x_hat =======================
constexpr int ROWS_O = 32;
constexpr int OS = 324;  // Wo row stride (81x16B -> conflict-free)
constexpr int OO_W  = 0;                    // 128*324
constexpr int OO_H  = OO_W + I_ * OS;       // 32*260
constexpr int OO_Z  = OO_H + ROWS_O * WS;   // 32*68
constexpr int OO_B  = OO_Z + ROWS_O * 68;   // 128
constexpr size_t SMEM_O = (size_t)(OO_B + 128) * sizeof(float);

__global__ __launch_bounds__(256, 1) void k_out(
    const float* __restrict__ Wo, const float* __restrict__ bo,
    float* __restrict__ out)
{
    extern __shared__ float sm[];
    float* sWo = sm + OO_W; float* sh = sm + OO_H; float* sz = sm + OO_Z; float* sbo = sm + OO_B;
    const int tid = threadIdx.x;
    const long bt0 = (long)blockIdx.x * ROWS_O;

    for (int idx = tid; idx < I_ * 320; idx += 256) {
        int i = idx / 320, c = idx - i * 320;
        sWo[i * OS + c] = Wo[idx];
    }
    for (int idx = tid; idx < ROWS_O * H_; idx += 256) {
        int r = idx >> 8, k = idx & 255;
        sh[r * WS + k] = g_H[bt0 * H_ + idx];
    }
    for (int idx = tid; idx < ROWS_O * L_; idx += 256) {
        int r = idx >> 6, n = idx & 63;
        sz[r * 68 + n] = g_Z[bt0 * L_ + idx];
    }
    if (tid < I_) sbo[tid] = bo[tid];
    __syncthreads();

    for (int task = tid; task < ROWS_O * I_; task += 256) {
        int r = task >> 7, i = task & 127;
        const float4* w4 = reinterpret_cast<const float4*>(sWo + i * OS);
        const float4* h4 = reinterpret_cast<const float4*>(sh + r * WS);
        const float4* z4 = reinterpret_cast<const float4*>(sz + r * 68);
        float acc = sbo[i];
        #pragma unroll 8
        for (int k = 0; k < H_ / 4; k++) {
            float4 wv = w4[k], hv = h4[k];
            acc += wv.x * hv.x + wv.y * hv.y + wv.z * hv.z + wv.w * hv.w;
        }
        #pragma unroll
        for (int k = 0; k < L_ / 4; k++) {
            float4 wv = w4[64 + k], zv = z4[k];
            acc += wv.x * zv.x + wv.y * zv.y + wv.z * zv.z + wv.w * zv.w;
        }
        out[XHAT_OFF + (bt0 + r) * I_ + i] = 1.0f / (1.0f + __expf(-acc));
    }
}

// ======================= launch =======================
extern "C" void kernel_launch(void* const* d_in, const int* in_sizes, int n_in,
                              void* d_out, int out_size) {
    const float* x      = (const float*)d_in[0];
    const float* hidden = (const float*)d_in[1];
    const float* noise  = (const float*)d_in[2];
    const float* Wpm1 = (const float*)d_in[3];  const float* bpm1 = (const float*)d_in[4];
    const float* Wpm2 = (const float*)d_in[5];  const float* bpm2 = (const float*)d_in[6];
    const float* Wpl1 = (const float*)d_in[7];  const float* bpl1 = (const float*)d_in[8];
    const float* Wpl2 = (const float*)d_in[9];  const float* bpl2 = (const float*)d_in[10];
    const float* Wqm1 = (const float*)d_in[11]; const float* bqm1 = (const float*)d_in[12];
    const float* Wqm2 = (const float*)d_in[13]; const float* bqm2 = (const float*)d_in[14];
    const float* Wql1 = (const float*)d_in[15]; const float* bql1 = (const float*)d_in[16];
    const float* Wql2 = (const float*)d_in[17]; const float* bql2 = (const float*)d_in[18];
    const float* Wh1  = (const float*)d_in[19]; const float* bh1  = (const float*)d_in[20];
    const float* Wh2  = (const float*)d_in[21]; const float* bh2  = (const float*)d_in[22];
    const float* Wo   = (const float*)d_in[23]; const float* bo   = (const float*)d_in[24];
    float* out = (float*)d_out;

    cudaFuncSetAttribute(k_pre,     cudaFuncAttributeMaxDynamicSharedMemorySize, (int)SMEM_PRE);
    cudaFuncSetAttribute(k_seq,     cudaFuncAttributeMaxDynamicSharedMemorySize, (int)SMEM_SEQ);
    cudaFuncSetAttribute(k_pbranch, cudaFuncAttributeMaxDynamicSharedMemorySize, (int)SMEM_P);
    cudaFuncSetAttribute(k_out,     cudaFuncAttributeMaxDynamicSharedMemorySize, (int)SMEM_O);

    k_pre<<<(int)(BT / ROWS_A), 256, SMEM_PRE>>>(x, Wqm1, bqm1, Wql1, bql1, Wh1, bh1);
    k_seq<<<B_ / 2, 256, SMEM_SEQ>>>(hidden, noise,
                                     Wqm1, Wqm2, bqm2, Wql1, Wql2, bql2,
                                     Wh1, Wh2, bh2, out);
    k_pbranch<<<(int)(BT / ROWS_P), 256, SMEM_P>>>(Wpm1, bpm1, Wpm2, bpm2,
                                                   Wpl1, bpl1, Wpl2, bpl2, out);
    k_out<<<(int)(BT / ROWS_O), 256, SMEM_O>>>(Wo, bo, out);
}

// round 8
// speedup vs baseline: 1.4385x; 1.4385x over previous
#include <cuda_runtime.h>
#include <cuda_fp16.h>
#include <math.h>

constexpr int  B_ = 256, T_ = 512, I_ = 128, H_ = 256, L_ = 64, P_ = 50;
constexpr long BT = (long)B_ * T_;
constexpr long PMU_OFF = BT * I_, PLV_OFF = PMU_OFF + BT * L_;
constexpr long QMU_OFF = PLV_OFF + BT * L_, QLV_OFF = QMU_OFF + BT * L_;

__device__ float g_H[BT * H_];
__device__ float g_Z[BT * L_];
__device__ float g_preQM[BT * P_];
__device__ float g_preQL[BT * P_];
__device__ float g_preH[BT * P_];

using u64 = unsigned long long;
__device__ __forceinline__ u64 pk(float x, float y) {
    u64 r; asm("mov.b64 %0,{%1,%2};" : "=l"(r) : "f"(x), "f"(y)); return r;
}
__device__ __forceinline__ float2 up(u64 v) {
    float2 f; asm("mov.b64 {%0,%1},%2;" : "=f"(f.x), "=f"(f.y) : "l"(v)); return f;
}
__device__ __forceinline__ u64 f2fma(u64 a, u64 b, u64 c) {
    u64 d; asm("fma.rn.f32x2 %0,%1,%2,%3;" : "=l"(d) : "l"(a), "l"(b), "l"(c)); return d;
}
__device__ __forceinline__ float hsum(u64 v) { float2 f = up(v); return f.x + f.y; }

// ===================== Phase A: x pre-projections =====================
constexpr int ROWS_A = 64, XS = 132;
constexpr size_t SMEM_PRE = (size_t)(3 * P_ * XS + ROWS_A * XS + 3 * 64) * sizeof(float);

__global__ __launch_bounds__(256, 1) void k_pre(
    const float* __restrict__ x,
    const float* __restrict__ Wqm1, const float* __restrict__ bqm1,
    const float* __restrict__ Wql1, const float* __restrict__ bql1,
    const float* __restrict__ Wh1,  const float* __restrict__ bh1)
{
    extern __shared__ float sm[];
    float* sw = sm; float* sx = sw + 3 * P_ * XS; float* sb = sx + ROWS_A * XS;
    const int tid = threadIdx.x;
    const long bt0 = (long)blockIdx.x * ROWS_A;

    for (int idx = tid; idx < P_ * I_; idx += 256) {
        int j = idx >> 7, i = idx & 127;
        sw[j * XS + i] = Wqm1[j * 384 + i];
        sw[(P_ + j) * XS + i] = Wql1[j * 384 + i];
        sw[(2 * P_ + j) * XS + i] = Wh1[j * 448 + i];
    }
    for (int idx = tid; idx < ROWS_A * I_; idx += 256)
        sx[(idx >> 7) * XS + (idx & 127)] = x[bt0 * I_ + idx];
    if (tid < P_) { sb[tid] = bqm1[tid]; sb[64 + tid] = bql1[tid]; sb[128 + tid] = bh1[tid]; }
    __syncthreads();

    // tile: 5 outputs x 4 rows; rows = rr*16+g
    for (int task = tid; task < 480; task += 256) {
        int og = task >> 4, g = task & 15;
        const float4* w4[5]; const float4* x4[4];
        #pragma unroll
        for (int q = 0; q < 5; q++) w4[q] = (const float4*)(sw + (og * 5 + q) * XS);
        #pragma unroll
        for (int rr = 0; rr < 4; rr++) x4[rr] = (const float4*)(sx + (rr * 16 + g) * XS);
        u64 acc[5][4];
        #pragma unroll
        for (int q = 0; q < 5; q++)
            #pragma unroll
            for (int rr = 0; rr < 4; rr++) acc[q][rr] = 0;
        #pragma unroll 4
        for (int k = 0; k < I_ / 4; k++) {
            float4 xv[4]; u64 xlo[4], xhi[4];
            #pragma unroll
            for (int rr = 0; rr < 4; rr++) {
                xv[rr] = x4[rr][k]; xlo[rr] = pk(xv[rr].x, xv[rr].y); xhi[rr] = pk(xv[rr].z, xv[rr].w);
            }
            #pragma unroll
            for (int q = 0; q < 5; q++) {
                float4 wv = w4[q][k]; u64 wlo = pk(wv.x, wv.y), whi = pk(wv.z, wv.w);
                #pragma unroll
                for (int rr = 0; rr < 4; rr++) {
                    acc[q][rr] = f2fma(wlo, xlo[rr], acc[q][rr]);
                    acc[q][rr] = f2fma(whi, xhi[rr], acc[q][rr]);
                }
            }
        }
        #pragma unroll
        for (int q = 0; q < 5; q++) {
            int o = og * 5 + q, m = o / P_, j = o - m * P_;
            float* dst = (m == 0) ? g_preQM : (m == 1) ? g_preQL : g_preH;
            float bias = sb[m * 64 + j];
            #pragma unroll
            for (int rr = 0; rr < 4; rr++)
                dst[(bt0 + rr * 16 + g) * P_ + j] = bias + hsum(acc[q][rr]);
        }
    }
}

// ===================== Phase B: sequential recurrence =====================
constexpr int WS = 260;
constexpr int O_W1 = 0, O_W2T = O_W1 + 3 * P_ * WS, O_B2 = O_W2T + 50 * 128;
constexpr int O_BH2 = O_B2 + 128, O_H = O_BH2 + 256, O_A1 = O_H + 4 * WS;
constexpr int O_VH = O_A1 + 200, O_AH = O_VH + 104, O_Z = O_AH + 104;
constexpr size_t SMEM_SEQ = (size_t)(O_Z + 136) * sizeof(float);

__global__ __launch_bounds__(256, 1) void k_seq(
    const float* __restrict__ hidden, const float* __restrict__ noise,
    const float* __restrict__ Wqm1, const float* __restrict__ Wqm2, const float* __restrict__ bqm2,
    const float* __restrict__ Wql1, const float* __restrict__ Wql2, const float* __restrict__ bql2,
    const float* __restrict__ Wh1,  const float* __restrict__ Wh2,  const float* __restrict__ bh2,
    float* __restrict__ out)
{
    extern __shared__ float sm[];
    float* sW1 = sm + O_W1; float* sW2t = sm + O_W2T; float* sb2 = sm + O_B2;
    float* sbh2 = sm + O_BH2; float* sH = sm + O_H; float* sA1 = sm + O_A1;
    float* sVH = sm + O_VH; float* sAH = sm + O_AH; float* sZ = sm + O_Z;

    const int tid = threadIdx.x;
    const int r0 = blockIdx.x * 2;

    for (int idx = tid; idx < P_ * H_; idx += 256) {
        int j = idx >> 8, k = idx & 255;
        sW1[j * WS + k] = Wqm1[j * 384 + 128 + k];
        sW1[(P_ + j) * WS + k] = Wql1[j * 384 + 128 + k];
        sW1[(2 * P_ + j) * WS + k] = Wh1[j * 448 + 128 + k];
    }
    for (int idx = tid; idx < L_ * P_; idx += 256) {
        int n = idx / P_, j = idx - n * P_;
        sW2t[j * 128 + 2 * n] = Wqm2[n * P_ + j];
        sW2t[j * 128 + 2 * n + 1] = Wql2[n * P_ + j];
    }
    if (tid < L_) { sb2[2 * tid] = bqm2[tid]; sb2[2 * tid + 1] = bql2[tid]; }
    if (tid < H_) sbh2[tid] = bh2[tid];
    for (int idx = tid; idx < 2 * H_; idx += 256)
        sH[(idx >> 8) * WS + (idx & 255)] = hidden[(r0 + (idx >> 8)) * H_ + (idx & 255)];
    if (tid == 0) { sAH[50] = sAH[51] = sAH[102] = sAH[103] = 0.f; }

    __half2 wh2c[52];  // all threads: {Wh2[2kp][j], Wh2[2kp+1][j]}
    {
        int kp = tid & 127;
        #pragma unroll
        for (int j = 0; j < 50; j++)
            wh2c[j] = __floats2half2_rn(Wh2[2 * kp * P_ + j], Wh2[(2 * kp + 1) * P_ + j]);
        wh2c[50] = wh2c[51] = __floats2half2_rn(0.f, 0.f);
    }
    __half2 wzc[32];   // tid<100: Wh1 z-block, row j = tid%50
    if (tid < 100) {
        int j = tid % 50;
        #pragma unroll
        for (int i = 0; i < 32; i++)
            wzc[i] = __floats2half2_rn(Wh1[j * 448 + 384 + 2 * i], Wh1[j * 448 + 384 + 2 * i + 1]);
    }
    __syncthreads();

    int cb = 0;
    for (int t = 0; t < T_; t++) {
        const long bt0 = (long)r0 * T_ + t, bt1 = bt0 + T_;
        float e0 = 0.f, e1 = 0.f;
        if (tid < 64) { e0 = noise[bt0 * L_ + tid]; e1 = noise[bt1 * L_ + tid]; }

        // s1: 100 threads, (r,j) each computes all 3 dots vs one h row
        if (tid < 100) {
            int r = tid & 1, j = tid >> 1;
            long bt = r ? bt1 : bt0;
            float p0 = g_preQM[bt * P_ + j], p1 = g_preQL[bt * P_ + j], p2 = g_preH[bt * P_ + j];
            const float4* h4 = (const float4*)(sH + (cb * 2 + r) * WS);
            const float4* w0 = (const float4*)(sW1 + j * WS);
            const float4* w1 = (const float4*)(sW1 + (P_ + j) * WS);
            const float4* w2 = (const float4*)(sW1 + (2 * P_ + j) * WS);
            u64 a0 = 0, a1 = 0, a2 = 0;
            #pragma unroll 8
            for (int k = 0; k < H_ / 4; k++) {
                float4 hv = h4[k]; u64 hlo = pk(hv.x, hv.y), hhi = pk(hv.z, hv.w);
                float4 v0 = w0[k]; a0 = f2fma(pk(v0.x, v0.y), hlo, a0); a0 = f2fma(pk(v0.z, v0.w), hhi, a0);
                float4 v1 = w1[k]; a1 = f2fma(pk(v1.x, v1.y), hlo, a1); a1 = f2fma(pk(v1.z, v1.w), hhi, a1);
                float4 v2 = w2[k]; a2 = f2fma(pk(v2.x, v2.y), hlo, a2); a2 = f2fma(pk(v2.z, v2.w), hhi, a2);
            }
            sA1[j * 4 + 2 * r]     = fmaxf(p0 + hsum(a0), 0.f);
            sA1[j * 4 + 2 * r + 1] = fmaxf(p1 + hsum(a1), 0.f);
            sVH[r * 52 + j] = p2 + hsum(a2);
        } else {
            for (int idx = tid - 100; idx < 2 * H_; idx += 156) {
                int r = idx >> 8, k = idx & 255;
                g_H[(r ? bt1 : bt0) * H_ + k] = sH[(cb * 2 + r) * WS + k];
            }
        }
        __syncthreads();

        // s2: q_mu,q_lv and z (64 threads, both rows)
        if (tid < 64) {
            int n = tid;
            u64 accA = pk(sb2[2 * n], sb2[2 * n + 1]), accB = accA;
            #pragma unroll 10
            for (int j = 0; j < 50; j++) {
                float2 w = *(const float2*)(sW2t + j * 128 + 2 * n);
                float4 a = *(const float4*)(sA1 + j * 4);
                u64 wp = pk(w.x, w.y);
                accA = f2fma(wp, pk(a.x, a.y), accA);
                accB = f2fma(wp, pk(a.z, a.w), accB);
            }
            float2 q0 = up(accA), q1 = up(accB);
            out[QMU_OFF + bt0 * L_ + n] = q0.x; out[QLV_OFF + bt0 * L_ + n] = q0.y;
            out[QMU_OFF + bt1 * L_ + n] = q1.x; out[QLV_OFF + bt1 * L_ + n] = q1.y;
            float z0 = q0.x + __expf(0.5f * q0.y) * e0;
            float z1 = q1.x + __expf(0.5f * q1.y) * e1;
            sZ[n] = z0; sZ[68 + n] = z1;
            g_Z[bt0 * L_ + n] = z0; g_Z[bt1 * L_ + n] = z1;
        }
        __syncthreads();

        // s3: add z-part (reg-cached fp16 Wz), relu
        if (tid < 100) {
            int r = tid / 50, j = tid - r * 50;
            const float4* z4 = (const float4*)(sZ + r * 68);
            u64 acc1 = 0, acc2 = 0;
            #pragma unroll
            for (int i = 0; i < 16; i++) {
                float4 z = z4[i];
                float2 wa = __half22float2(wzc[2 * i]);
                float2 wb = __half22float2(wzc[2 * i + 1]);
                acc1 = f2fma(pk(wa.x, wa.y), pk(z.x, z.y), acc1);
                acc2 = f2fma(pk(wb.x, wb.y), pk(z.z, z.w), acc2);
            }
            sAH[r * 52 + j] = fmaxf(sVH[r * 52 + j] + hsum(acc1) + hsum(acc2), 0.f);
        }
        __syncthreads();

        // s4: h_next = Wh2 @ a + bh2 (reg-cached fp16 Wh2)
        {
            int r = tid >> 7, kp = tid & 127;
            const float4* a4 = (const float4*)(sAH + r * 52);
            float2 bb = *(const float2*)(sbh2 + 2 * kp);
            u64 acc = pk(bb.x, bb.y), acc2 = 0;
            #pragma unroll
            for (int q = 0; q < 13; q++) {
                float4 av = a4[q];
                float2 w0 = __half22float2(wh2c[4 * q]);     acc  = f2fma(pk(w0.x, w0.y), pk(av.x, av.x), acc);
                float2 w1 = __half22float2(wh2c[4 * q + 1]); acc2 = f2fma(pk(w1.x, w1.y), pk(av.y, av.y), acc2);
                float2 w2 = __half22float2(wh2c[4 * q + 2]); acc  = f2fma(pk(w2.x, w2.y), pk(av.z, av.z), acc);
                float2 w3 = __half22float2(wh2c[4 * q + 3]); acc2 = f2fma(pk(w3.x, w3.y), pk(av.w, av.w), acc2);
            }
            float2 r1 = up(acc), r2 = up(acc2);
            int nb = cb ^ 1;
            *(float2*)(sH + (nb * 2 + r) * WS + 2 * kp) = make_float2(r1.x + r2.x, r1.y + r2.y);
        }
        __syncthreads();
        cb ^= 1;
    }
}

// ===================== Phase C1: p-branch MLPs =====================
constexpr int ROWS_P = 32;
constexpr int PO_W1 = 0, PO_W2 = PO_W1 + 2 * P_ * WS, PO_B1 = PO_W2 + 2 * L_ * P_;
constexpr int PO_B2 = PO_B1 + 128, PO_H = PO_B2 + 128, PO_A = PO_H + ROWS_P * WS;
constexpr size_t SMEM_P = (size_t)(PO_A + 2 * ROWS_P * 52) * sizeof(float);

__global__ __launch_bounds__(256, 1) void k_pbranch(
    const float* __restrict__ Wpm1, const float* __restrict__ bpm1,
    const float* __restrict__ Wpm2, const float* __restrict__ bpm2,
    const float* __restrict__ Wpl1, const float* __restrict__ bpl1,
    const float* __restrict__ Wpl2, const float* __restrict__ bpl2,
    float* __restrict__ out)
{
    extern __shared__ float sm[];
    float* sW1 = sm + PO_W1; float* sW2 = sm + PO_W2; float* sb1 = sm + PO_B1;
    float* sb2 = sm + PO_B2; float* sh = sm + PO_H; float* sa = sm + PO_A;
    const int tid = threadIdx.x;
    const long bt0 = (long)blockIdx.x * ROWS_P;

    for (int idx = tid; idx < P_ * H_; idx += 256) {
        int j = idx >> 8, k = idx & 255;
        sW1[j * WS + k] = Wpm1[idx];
        sW1[(P_ + j) * WS + k] = Wpl1[idx];
    }
    for (int idx = tid; idx < L_ * P_; idx += 256) {
        sW2[idx] = Wpm2[idx]; sW2[L_ * P_ + idx] = Wpl2[idx];
    }
    if (tid < P_) { sb1[tid] = bpm1[tid]; sb1[64 + tid] = bpl1[tid]; }
    if (tid < L_) { sb2[tid] = bpm2[tid]; sb2[64 + tid] = bpl2[tid]; }
    for (int idx = tid; idx < ROWS_P * H_; idx += 256)
        sh[(idx >> 8) * WS + (idx & 255)] = g_H[bt0 * H_ + idx];
    __syncthreads();

    // layer1 tile: 4 outputs x 8 rows; rows = rr*4+g (100 tasks)
    if (tid < 100) {
        int op = tid >> 2, g = tid & 3;
        const float4* w4[4]; const float4* h4[8];
        #pragma unroll
        for (int q = 0; q < 4; q++) w4[q] = (const float4*)(sW1 + (op * 4 + q) * WS);
        #pragma unroll
        for (int rr = 0; rr < 8; rr++) h4[rr] = (const float4*)(sh + (rr * 4 + g) * WS);
        u64 acc[4][8];
        #pragma unroll
        for (int q = 0; q < 4; q++)
            #pragma unroll
            for (int rr = 0; rr < 8; rr++) acc[q][rr] = 0;
        #pragma unroll 4
        for (int k = 0; k < H_ / 4; k++) {
            u64 hlo[8], hhi[8];
            #pragma unroll
            for (int rr = 0; rr < 8; rr++) {
                float4 hv = h4[rr][k]; hlo[rr] = pk(hv.x, hv.y); hhi[rr] = pk(hv.z, hv.w);
            }
            #pragma unroll
            for (int q = 0; q < 4; q++) {
                float4 wv = w4[q][k]; u64 wlo = pk(wv.x, wv.y), whi = pk(wv.z, wv.w);
                #pragma unroll
                for (int rr = 0; rr < 8; rr++) {
                    acc[q][rr] = f2fma(wlo, hlo[rr], acc[q][rr]);
                    acc[q][rr] = f2fma(whi, hhi[rr], acc[q][rr]);
                }
            }
        }
        #pragma unroll
        for (int q = 0; q < 4; q++) {
            int o = op * 4 + q, m = o / P_, j = o - m * P_;
            float bias = sb1[m * 64 + j];
            #pragma unroll
            for (int rr = 0; rr < 8; rr++)
                sa[(m * ROWS_P + rr * 4 + g) * 52 + j] = fmaxf(bias + hsum(acc[q][rr]), 0.f);
        }
    }
    __syncthreads();

    for (int task = tid; task < 2 * ROWS_P * L_; task += 256) {
        int m = task / (ROWS_P * L_); int rn = task - m * ROWS_P * L_;
        int r = rn >> 6, n = rn & 63;
        const float* w = sW2 + (m * L_ + n) * P_;
        const float* a = sa + (m * ROWS_P + r) * 52;
        float acc = sb2[m * 64 + n];
        #pragma unroll
        for (int j = 0; j < P_; j++) acc += w[j] * a[j];
        out[((m == 0) ? PMU_OFF : PLV_OFF) + (bt0 + r) * L_ + n] = acc;
    }
}

// ===================== Phase C2: x_hat =====================
constexpr int ROWS_O = 32, OS = 324;
constexpr int OO_W = 0, OO_H = OO_W + I_ * OS, OO_Z = OO_H + ROWS_O * WS;
constexpr int OO_B = OO_Z + ROWS_O * 68;
constexpr size_t SMEM_O = (size_t)(OO_B + 128) * sizeof(float);

__global__ __launch_bounds__(128, 1) void k_out(
    const float* __restrict__ Wo, const float* __restrict__ bo, float* __restrict__ out)
{
    extern __shared__ float sm[];
    float* sWo = sm + OO_W; float* sh = sm + OO_H; float* sz = sm + OO_Z; float* sbo = sm + OO_B;
    const int tid = threadIdx.x;
    const long bt0 = (long)blockIdx.x * ROWS_O;

    for (int idx = tid; idx < I_ * 320; idx += 128) {
        int i = idx / 320, c = idx - i * 320;
        sWo[i * OS + c] = Wo[idx];
    }
    for (int idx = tid; idx < ROWS_O * H_; idx += 128)
        sh[(idx >> 8) * WS + (idx & 255)] = g_H[bt0 * H_ + idx];
    for (int idx = tid; idx < ROWS_O * L_; idx += 128)
        sz[(idx >> 6) * 68 + (idx & 63)] = g_Z[bt0 * L_ + idx];
    if (tid < I_) sbo[tid] = bo[tid];
    __syncthreads();

    // tile: 4 outputs x 8 rows; rows = rr*4+g (128 tasks)
    {
        int ig = tid >> 2, g = tid & 3;
        const float4* w4[4]; const float4* h4[8]; const float4* z4[8];
        #pragma unroll
        for (int q = 0; q < 4; q++) w4[q] = (const float4*)(sWo + (ig * 4 + q) * OS);
        #pragma unroll
        for (int rr = 0; rr < 8; rr++) {
            h4[rr] = (const float4*)(sh + (rr * 4 + g) * WS);
            z4[rr] = (const float4*)(sz + (rr * 4 + g) * 68);
        }
        u64 acc[4][8];
        #pragma unroll
        for (int q = 0; q < 4; q++)
            #pragma unroll
            for (int rr = 0; rr < 8; rr++) acc[q][rr] = 0;
        #pragma unroll 4
        for (int k = 0; k < H_ / 4; k++) {
            u64 hlo[8], hhi[8];
            #pragma unroll
            for (int rr = 0; rr < 8; rr++) {
                float4 hv = h4[rr][k]; hlo[rr] = pk(hv.x, hv.y); hhi[rr] = pk(hv.z, hv.w);
            }
            #pragma unroll
            for (int q = 0; q < 4; q++) {
                float4 wv = w4[q][k]; u64 wlo = pk(wv.x, wv.y), whi = pk(wv.z, wv.w);
                #pragma unroll
                for (int rr = 0; rr < 8; rr++) {
                    acc[q][rr] = f2fma(wlo, hlo[rr], acc[q][rr]);
                    acc[q][rr] = f2fma(whi, hhi[rr], acc[q][rr]);
                }
            }
        }
        #pragma unroll
        for (int k = 0; k < L_ / 4; k++) {
            u64 zlo[8], zhi[8];
            #pragma unroll
            for (int rr = 0; rr < 8; rr++) {
                float4 zv = z4[rr][k]; zlo[rr] = pk(zv.x, zv.y); zhi[rr] = pk(zv.z, zv.w);
            }
            #pragma unroll
            for (int q = 0; q < 4; q++) {
                float4 wv = w4[q][64 + k]; u64 wlo = pk(wv.x, wv.y), whi = pk(wv.z, wv.w);
                #pragma unroll
                for (int rr = 0; rr < 8; rr++) {
                    acc[q][rr] = f2fma(wlo, zlo[rr], acc[q][rr]);
                    acc[q][rr] = f2fma(whi, zhi[rr], acc[q][rr]);
                }
            }
        }
        #pragma unroll
        for (int q = 0; q < 4; q++) {
            int i = ig * 4 + q; float bias = sbo[i];
            #pragma unroll
            for (int rr = 0; rr < 8; rr++) {
                float v = bias + hsum(acc[q][rr]);
                out[(bt0 + rr * 4 + g) * I_ + i] = 1.0f / (1.0f + __expf(-v));
            }
        }
    }
}

// ===================== launch =====================
extern "C" void kernel_launch(void* const* d_in, const int* in_sizes, int n_in,
                              void* d_out, int out_size) {
    const float* x = (const float*)d_in[0];
    const float* hidden = (const float*)d_in[1];
    const float* noise = (const float*)d_in[2];
    const float* Wpm1 = (const float*)d_in[3];  const float* bpm1 = (const float*)d_in[4];
    const float* Wpm2 = (const float*)d_in[5];  const float* bpm2 = (const float*)d_in[6];
    const float* Wpl1 = (const float*)d_in[7];  const float* bpl1 = (const float*)d_in[8];
    const float* Wpl2 = (const float*)d_in[9];  const float* bpl2 = (const float*)d_in[10];
    const float* Wqm1 = (const float*)d_in[11]; const float* bqm1 = (const float*)d_in[12];
    const float* Wqm2 = (const float*)d_in[13]; const float* bqm2 = (const float*)d_in[14];
    const float* Wql1 = (const float*)d_in[15]; const float* bql1 = (const float*)d_in[16];
    const float* Wql2 = (const float*)d_in[17]; const float* bql2 = (const float*)d_in[18];
    const float* Wh1 = (const float*)d_in[19];  const float* bh1 = (const float*)d_in[20];
    const float* Wh2 = (const float*)d_in[21];  const float* bh2 = (const float*)d_in[22];
    const float* Wo = (const float*)d_in[23];   const float* bo = (const float*)d_in[24];
    float* out = (float*)d_out;

    cudaFuncSetAttribute(k_pre, cudaFuncAttributeMaxDynamicSharedMemorySize, (int)SMEM_PRE);
    cudaFuncSetAttribute(k_seq, cudaFuncAttributeMaxDynamicSharedMemorySize, (int)SMEM_SEQ);
    cudaFuncSetAttribute(k_pbranch, cudaFuncAttributeMaxDynamicSharedMemorySize, (int)SMEM_P);
    cudaFuncSetAttribute(k_out, cudaFuncAttributeMaxDynamicSharedMemorySize, (int)SMEM_O);

    k_pre<<<(int)(BT / ROWS_A), 256, SMEM_PRE>>>(x, Wqm1, bqm1, Wql1, bql1, Wh1, bh1);
    k_seq<<<B_ / 2, 256, SMEM_SEQ>>>(hidden, noise, Wqm1, Wqm2, bqm2,
                                     Wql1, Wql2, bql2, Wh1, Wh2, bh2, out);
    k_pbranch<<<(int)(BT / ROWS_P), 256, SMEM_P>>>(Wpm1, bpm1, Wpm2, bpm2,
                                                   Wpl1, bpl1, Wpl2, bpl2, out);
    k_out<<<(int)(BT / ROWS_O), 128, SMEM_O>>>(Wo, bo, out);
}